// round 8
// baseline (speedup 1.0000x reference)
#include <cuda_runtime.h>

// GC_3D loss: BCE(mean) + 1 - (1/13) * sum_k [ sum(di_k*dt_k) / (sum(dt_k^2)+1e-5) ]
// Shape (4,1,128,192,192) f32, forward-z canonical offsets.
// R8: ZCHUNKS=16 (wave balancing), float4+4-accum unrolled finalize.

#define DX 192
#define DY 192
#define DZ 128
#define DXY (DX * DY)
#define NX4 48
#define NSUM 27
#define ZCHUNKS 16
#define ZSTEP (DZ / ZCHUNKS)   // 8
#define NBLK 4608               // 589824 threads / 128

__device__ float g_part[NSUM][NBLK];   // fully overwritten each run

__device__ __forceinline__ void ldwin(const float* __restrict__ p,
                                      int o_m1, int o_p4, float w[6]) {
    float4 v = *reinterpret_cast<const float4*>(p);
    w[0] = __ldg(p + o_m1);   // x-edge: o_m1=0 -> w[0]=center -> diff 0
    w[1] = v.x; w[2] = v.y; w[3] = v.z; w[4] = v.w;
    w[5] = __ldg(p + o_p4);   // x-edge: o_p4=3 -> w[5]=center -> diff 0
}

// One (row,dx) offset: 4 diffs per array. G: multiply dt by row flag (y-edge path only).
#define ACCUM(WI, WT, J, G, RF, D, Q) do {                                  \
    float di0 = (WI)[(J)]   - cI0; float dt0 = ((WT)[(J)]   - cT0);         \
    float di1 = (WI)[(J)+1] - cI1; float dt1 = ((WT)[(J)+1] - cT1);         \
    float di2 = (WI)[(J)+2] - cI2; float dt2 = ((WT)[(J)+2] - cT2);         \
    float di3 = (WI)[(J)+3] - cI3; float dt3 = ((WT)[(J)+3] - cT3);         \
    if (G) { dt0 *= (RF); dt1 *= (RF); dt2 *= (RF); dt3 *= (RF); }          \
    D = fmaf(di0, dt0, D); D = fmaf(di1, dt1, D);                           \
    D = fmaf(di2, dt2, D); D = fmaf(di3, dt3, D);                           \
    Q = fmaf(dt0, dt0, Q); Q = fmaf(dt1, dt1, Q);                           \
    Q = fmaf(dt2, dt2, Q); Q = fmaf(dt3, dt3, Q);                           \
} while (0)

#define ROW3(WI, WT, G, RF, K) do {                                         \
    ACCUM(WI, WT, 0, G, RF, dot[(K)],   den[(K)]);                          \
    ACCUM(WI, WT, 1, G, RF, dot[(K)+1], den[(K)+1]);                        \
    ACCUM(WI, WT, 2, G, RF, dot[(K)+2], den[(K)+2]);                        \
} while (0)

// BCE partial in log2 domain: lg2(1-i) + t*(lg2(i)-lg2(1-i))
#define BCE4(CI, CT) do {                                                   \
    float l1, l2;                                                           \
    l1 = __log2f(CI[1]); l2 = __log2f(1.0f - CI[1]); bce += l2 + CT[1]*(l1-l2); \
    l1 = __log2f(CI[2]); l2 = __log2f(1.0f - CI[2]); bce += l2 + CT[2]*(l1-l2); \
    l1 = __log2f(CI[3]); l2 = __log2f(1.0f - CI[3]); bce += l2 + CT[3]*(l1-l2); \
    l1 = __log2f(CI[4]); l2 = __log2f(1.0f - CI[4]); bce += l2 + CT[4]*(l1-l2); \
} while (0)

template<bool YG>
__device__ __forceinline__ void gc3d_march(
    const float* __restrict__ in, const float* __restrict__ tg,
    int base, int nsteps, bool do_epi,
    int o_m1, int o_p4, int dUp, int dDn,
    float fym, float fyp,
    float* dot, float* den, float& bce)
{
    float CWi[6], CWt[6], UWi[6], UWt[6];      // carried: center row, y+1 row
    ldwin(in + base,       o_m1, o_p4, CWi);
    ldwin(tg + base,       o_m1, o_p4, CWt);
    ldwin(in + base + dUp, o_m1, o_p4, UWi);
    ldwin(tg + base + dUp, o_m1, o_p4, UWt);

#pragma unroll 2
    for (int s = 0; s < nsteps; ++s) {
        const int baseN = base + DXY;
        float NmI[6], NmT[6], NcI[6], NcT[6], NpI[6], NpT[6];
        ldwin(in + baseN + dDn, o_m1, o_p4, NmI);
        ldwin(tg + baseN + dDn, o_m1, o_p4, NmT);
        ldwin(in + baseN,       o_m1, o_p4, NcI);
        ldwin(tg + baseN,       o_m1, o_p4, NcT);
        ldwin(in + baseN + dUp, o_m1, o_p4, NpI);
        ldwin(tg + baseN + dUp, o_m1, o_p4, NpT);

        const float cI0 = CWi[1], cI1 = CWi[2], cI2 = CWi[3], cI3 = CWi[4];
        const float cT0 = CWt[1], cT1 = CWt[2], cT2 = CWt[3], cT3 = CWt[4];

        BCE4(CWi, CWt);

        // k0: (0,0,+1) on center row — x-edges self-zero
        ACCUM(CWi, CWt, 2, false, 1.0f, dot[0], den[0]);
        // k1..3: (0,1,dx) on carried y+1 row
        ROW3(UWi, UWt, YG, fyp, 1);
        // k4..6: (1,-1,dx)
        ROW3(NmI, NmT, YG, fym, 4);
        // k7..9: (1,0,dx)
        ROW3(NcI, NcT, false, 1.0f, 7);
        // k10..12: (1,1,dx)
        ROW3(NpI, NpT, YG, fyp, 10);

#pragma unroll
        for (int j = 0; j < 6; ++j) {
            CWi[j] = NcI[j]; CWt[j] = NcT[j];
            UWi[j] = NpI[j]; UWt[j] = NpT[j];
        }
        base = baseN;
    }

    if (do_epi) {  // z = 127: only dz=0 offsets; no fresh loads
        const float cI0 = CWi[1], cI1 = CWi[2], cI2 = CWi[3], cI3 = CWi[4];
        const float cT0 = CWt[1], cT1 = CWt[2], cT2 = CWt[3], cT3 = CWt[4];
        BCE4(CWi, CWt);
        ACCUM(CWi, CWt, 2, false, 1.0f, dot[0], den[0]);
        ROW3(UWi, UWt, YG, fyp, 1);
    }
}

__global__ void __launch_bounds__(128) gc3d_main_kernel(
    const float* __restrict__ in, const float* __restrict__ tg)
{
    const int tid = blockIdx.x * blockDim.x + threadIdx.x;   // 0..589823
    const int x4 = tid % NX4;
    const int y  = (tid / NX4) % DY;
    const int t2 = tid / (NX4 * DY);   // 0..63
    const int zc = t2 & (ZCHUNKS - 1);
    const int b  = t2 / ZCHUNKS;
    const int z0 = zc * ZSTEP;

    int base = ((b * DZ + z0) * DY + y) * DX + x4 * 4;

    const int   o_m1 = (x4 == 0)       ? 0 : -1;
    const int   o_p4 = (x4 == NX4 - 1) ? 3 : 4;
    const int   dUp  = (y == DY - 1) ? 0 : DX;
    const int   dDn  = (y == 0)      ? 0 : -DX;
    const float fyp  = (y == DY - 1) ? 0.0f : 1.0f;
    const float fym  = (y == 0)      ? 0.0f : 1.0f;

    const int  nsteps = (zc == ZCHUNKS - 1) ? (ZSTEP - 1) : ZSTEP;
    const bool do_epi = (zc == ZCHUNKS - 1);

    float dot[13], den[13], bce = 0.0f;
#pragma unroll
    for (int k = 0; k < 13; ++k) { dot[k] = 0.0f; den[k] = 0.0f; }

    if (y == 0 || y == DY - 1)
        gc3d_march<true >(in, tg, base, nsteps, do_epi, o_m1, o_p4, dUp, dDn,
                          fym, fyp, dot, den, bce);
    else
        gc3d_march<false>(in, tg, base, nsteps, do_epi, o_m1, o_p4, dUp, dDn,
                          fym, fyp, dot, den, bce);

    // pack 27 partials, warp butterfly, block reduce, overwrite block slot
    float acc[NSUM];
#pragma unroll
    for (int k = 0; k < 13; ++k) { acc[k] = dot[k]; acc[13 + k] = den[k]; }
    acc[26] = bce;

#pragma unroll
    for (int i = 0; i < NSUM; ++i) {
        float v = acc[i];
#pragma unroll
        for (int o = 16; o > 0; o >>= 1) v += __shfl_xor_sync(0xFFFFFFFFu, v, o);
        acc[i] = v;
    }

    __shared__ float sh[4][NSUM];
    const int wid = threadIdx.x >> 5;
    const int lid = threadIdx.x & 31;
    if (lid == 0) {
#pragma unroll
        for (int i = 0; i < NSUM; ++i) sh[wid][i] = acc[i];
    }
    __syncthreads();
    if (wid == 0 && lid < NSUM) {
        g_part[lid][blockIdx.x] = sh[0][lid] + sh[1][lid] + sh[2][lid] + sh[3][lid];
    }
}

// 27 warps: warp i reduces g_part[i][*]. float4 loads, 4 independent double
// accumulators, fully unrolled -> all LDGs batched (MLP), short DADD chains.
__global__ void __launch_bounds__(864) gc3d_finalize_kernel(float* out, double inv_n) {
    const int wid = threadIdx.x >> 5;
    const int lid = threadIdx.x & 31;

    double d0 = 0.0, d1 = 0.0, d2 = 0.0, d3 = 0.0;
    if (wid < NSUM) {
        const float4* row = reinterpret_cast<const float4*>(g_part[wid]);
#pragma unroll
        for (int j = 0; j < NBLK / 4 / 32; ++j) {       // 36 iterations
            float4 v = __ldg(row + lid + 32 * j);
            d0 += (double)v.x; d1 += (double)v.y;
            d2 += (double)v.z; d3 += (double)v.w;
        }
    }
    double s = (d0 + d1) + (d2 + d3);
#pragma unroll
    for (int o = 16; o > 0; o >>= 1) s += __shfl_xor_sync(0xFFFFFFFFu, s, o);

    __shared__ double sums[NSUM];
    __shared__ double ratios[13];
    if (wid < NSUM && lid == 0) sums[wid] = s;
    __syncthreads();

    if (threadIdx.x < 13)
        ratios[threadIdx.x] = sums[threadIdx.x] / (sums[13 + threadIdx.x] + 1e-5);
    __syncthreads();

    if (threadIdx.x == 0) {
        double accv = 0.0;
#pragma unroll
        for (int k = 0; k < 13; ++k) accv += ratios[k];
        const double bce = -sums[26] * inv_n * 0.6931471805599453; // log2 -> ln
        out[0] = (float)(bce + 1.0 - accv / 13.0);
    }
}

extern "C" void kernel_launch(void* const* d_in, const int* in_sizes, int n_in,
                              void* d_out, int out_size)
{
    const float* in = (const float*)d_in[0];
    const float* tg = (const float*)d_in[1];
    float* out = (float*)d_out;
    const int n = in_sizes[0];   // 18874368

    gc3d_main_kernel<<<NBLK, 128>>>(in, tg);
    gc3d_finalize_kernel<<<1, 864>>>(out, 1.0 / (double)n);
}

// round 9
// speedup vs baseline: 1.7864x; 1.7864x over previous
#include <cuda_runtime.h>

// GC_3D loss: BCE(mean) + 1 - (1/13) * sum_k [ sum(di_k*dt_k) / (sum(dt_k^2)+1e-5) ]
// Shape (4,1,128,192,192) f32, forward-z canonical offsets.
// R9: R8 main (ZCHUNKS=16) + finalize reduced in f32 (FP64 only in the
//     27x5 butterfly + 13 divides) — FP64 throughput was the R8 regression.

#define DX 192
#define DY 192
#define DZ 128
#define DXY (DX * DY)
#define NX4 48
#define NSUM 27
#define ZCHUNKS 16
#define ZSTEP (DZ / ZCHUNKS)   // 8
#define NBLK 4608               // 589824 threads / 128

__device__ float g_part[NSUM][NBLK];   // fully overwritten each run

__device__ __forceinline__ void ldwin(const float* __restrict__ p,
                                      int o_m1, int o_p4, float w[6]) {
    float4 v = *reinterpret_cast<const float4*>(p);
    w[0] = __ldg(p + o_m1);   // x-edge: o_m1=0 -> w[0]=center -> diff 0
    w[1] = v.x; w[2] = v.y; w[3] = v.z; w[4] = v.w;
    w[5] = __ldg(p + o_p4);   // x-edge: o_p4=3 -> w[5]=center -> diff 0
}

// One (row,dx) offset: 4 diffs per array. G: multiply dt by row flag (y-edge path only).
#define ACCUM(WI, WT, J, G, RF, D, Q) do {                                  \
    float di0 = (WI)[(J)]   - cI0; float dt0 = ((WT)[(J)]   - cT0);         \
    float di1 = (WI)[(J)+1] - cI1; float dt1 = ((WT)[(J)+1] - cT1);         \
    float di2 = (WI)[(J)+2] - cI2; float dt2 = ((WT)[(J)+2] - cT2);         \
    float di3 = (WI)[(J)+3] - cI3; float dt3 = ((WT)[(J)+3] - cT3);         \
    if (G) { dt0 *= (RF); dt1 *= (RF); dt2 *= (RF); dt3 *= (RF); }          \
    D = fmaf(di0, dt0, D); D = fmaf(di1, dt1, D);                           \
    D = fmaf(di2, dt2, D); D = fmaf(di3, dt3, D);                           \
    Q = fmaf(dt0, dt0, Q); Q = fmaf(dt1, dt1, Q);                           \
    Q = fmaf(dt2, dt2, Q); Q = fmaf(dt3, dt3, Q);                           \
} while (0)

#define ROW3(WI, WT, G, RF, K) do {                                         \
    ACCUM(WI, WT, 0, G, RF, dot[(K)],   den[(K)]);                          \
    ACCUM(WI, WT, 1, G, RF, dot[(K)+1], den[(K)+1]);                        \
    ACCUM(WI, WT, 2, G, RF, dot[(K)+2], den[(K)+2]);                        \
} while (0)

// BCE partial in log2 domain: lg2(1-i) + t*(lg2(i)-lg2(1-i))
#define BCE4(CI, CT) do {                                                   \
    float l1, l2;                                                           \
    l1 = __log2f(CI[1]); l2 = __log2f(1.0f - CI[1]); bce += l2 + CT[1]*(l1-l2); \
    l1 = __log2f(CI[2]); l2 = __log2f(1.0f - CI[2]); bce += l2 + CT[2]*(l1-l2); \
    l1 = __log2f(CI[3]); l2 = __log2f(1.0f - CI[3]); bce += l2 + CT[3]*(l1-l2); \
    l1 = __log2f(CI[4]); l2 = __log2f(1.0f - CI[4]); bce += l2 + CT[4]*(l1-l2); \
} while (0)

template<bool YG>
__device__ __forceinline__ void gc3d_march(
    const float* __restrict__ in, const float* __restrict__ tg,
    int base, int nsteps, bool do_epi,
    int o_m1, int o_p4, int dUp, int dDn,
    float fym, float fyp,
    float* dot, float* den, float& bce)
{
    float CWi[6], CWt[6], UWi[6], UWt[6];      // carried: center row, y+1 row
    ldwin(in + base,       o_m1, o_p4, CWi);
    ldwin(tg + base,       o_m1, o_p4, CWt);
    ldwin(in + base + dUp, o_m1, o_p4, UWi);
    ldwin(tg + base + dUp, o_m1, o_p4, UWt);

#pragma unroll 2
    for (int s = 0; s < nsteps; ++s) {
        const int baseN = base + DXY;
        float NmI[6], NmT[6], NcI[6], NcT[6], NpI[6], NpT[6];
        ldwin(in + baseN + dDn, o_m1, o_p4, NmI);
        ldwin(tg + baseN + dDn, o_m1, o_p4, NmT);
        ldwin(in + baseN,       o_m1, o_p4, NcI);
        ldwin(tg + baseN,       o_m1, o_p4, NcT);
        ldwin(in + baseN + dUp, o_m1, o_p4, NpI);
        ldwin(tg + baseN + dUp, o_m1, o_p4, NpT);

        const float cI0 = CWi[1], cI1 = CWi[2], cI2 = CWi[3], cI3 = CWi[4];
        const float cT0 = CWt[1], cT1 = CWt[2], cT2 = CWt[3], cT3 = CWt[4];

        BCE4(CWi, CWt);

        // k0: (0,0,+1) on center row — x-edges self-zero
        ACCUM(CWi, CWt, 2, false, 1.0f, dot[0], den[0]);
        // k1..3: (0,1,dx) on carried y+1 row
        ROW3(UWi, UWt, YG, fyp, 1);
        // k4..6: (1,-1,dx)
        ROW3(NmI, NmT, YG, fym, 4);
        // k7..9: (1,0,dx)
        ROW3(NcI, NcT, false, 1.0f, 7);
        // k10..12: (1,1,dx)
        ROW3(NpI, NpT, YG, fyp, 10);

#pragma unroll
        for (int j = 0; j < 6; ++j) {
            CWi[j] = NcI[j]; CWt[j] = NcT[j];
            UWi[j] = NpI[j]; UWt[j] = NpT[j];
        }
        base = baseN;
    }

    if (do_epi) {  // z = 127: only dz=0 offsets; no fresh loads
        const float cI0 = CWi[1], cI1 = CWi[2], cI2 = CWi[3], cI3 = CWi[4];
        const float cT0 = CWt[1], cT1 = CWt[2], cT2 = CWt[3], cT3 = CWt[4];
        BCE4(CWi, CWt);
        ACCUM(CWi, CWt, 2, false, 1.0f, dot[0], den[0]);
        ROW3(UWi, UWt, YG, fyp, 1);
    }
}

__global__ void __launch_bounds__(128) gc3d_main_kernel(
    const float* __restrict__ in, const float* __restrict__ tg)
{
    const int tid = blockIdx.x * blockDim.x + threadIdx.x;   // 0..589823
    const int x4 = tid % NX4;
    const int y  = (tid / NX4) % DY;
    const int t2 = tid / (NX4 * DY);   // 0..63
    const int zc = t2 & (ZCHUNKS - 1);
    const int b  = t2 / ZCHUNKS;
    const int z0 = zc * ZSTEP;

    int base = ((b * DZ + z0) * DY + y) * DX + x4 * 4;

    const int   o_m1 = (x4 == 0)       ? 0 : -1;
    const int   o_p4 = (x4 == NX4 - 1) ? 3 : 4;
    const int   dUp  = (y == DY - 1) ? 0 : DX;
    const int   dDn  = (y == 0)      ? 0 : -DX;
    const float fyp  = (y == DY - 1) ? 0.0f : 1.0f;
    const float fym  = (y == 0)      ? 0.0f : 1.0f;

    const int  nsteps = (zc == ZCHUNKS - 1) ? (ZSTEP - 1) : ZSTEP;
    const bool do_epi = (zc == ZCHUNKS - 1);

    float dot[13], den[13], bce = 0.0f;
#pragma unroll
    for (int k = 0; k < 13; ++k) { dot[k] = 0.0f; den[k] = 0.0f; }

    if (y == 0 || y == DY - 1)
        gc3d_march<true >(in, tg, base, nsteps, do_epi, o_m1, o_p4, dUp, dDn,
                          fym, fyp, dot, den, bce);
    else
        gc3d_march<false>(in, tg, base, nsteps, do_epi, o_m1, o_p4, dUp, dDn,
                          fym, fyp, dot, den, bce);

    // pack 27 partials, warp butterfly, block reduce, overwrite block slot
    float acc[NSUM];
#pragma unroll
    for (int k = 0; k < 13; ++k) { acc[k] = dot[k]; acc[13 + k] = den[k]; }
    acc[26] = bce;

#pragma unroll
    for (int i = 0; i < NSUM; ++i) {
        float v = acc[i];
#pragma unroll
        for (int o = 16; o > 0; o >>= 1) v += __shfl_xor_sync(0xFFFFFFFFu, v, o);
        acc[i] = v;
    }

    __shared__ float sh[4][NSUM];
    const int wid = threadIdx.x >> 5;
    const int lid = threadIdx.x & 31;
    if (lid == 0) {
#pragma unroll
        for (int i = 0; i < NSUM; ++i) sh[wid][i] = acc[i];
    }
    __syncthreads();
    if (wid == 0 && lid < NSUM) {
        g_part[lid][blockIdx.x] = sh[0][lid] + sh[1][lid] + sh[2][lid] + sh[3][lid];
    }
}

// 27 warps: warp i reduces g_part[i][*]. float4 loads + FLOAT accumulation
// (FP64 is ~18 cyc/warp-op on B300 — keep it out of the O(N) path);
// double only for the 5-step butterfly and the 13 divides.
__global__ void __launch_bounds__(864) gc3d_finalize_kernel(float* out, double inv_n) {
    const int wid = threadIdx.x >> 5;
    const int lid = threadIdx.x & 31;

    float f0 = 0.0f, f1 = 0.0f, f2 = 0.0f, f3 = 0.0f;
    if (wid < NSUM) {
        const float4* row = reinterpret_cast<const float4*>(g_part[wid]);
#pragma unroll
        for (int j = 0; j < NBLK / 4 / 32; ++j) {       // 36 iterations
            float4 v = __ldg(row + lid + 32 * j);
            f0 += v.x; f1 += v.y; f2 += v.z; f3 += v.w;
        }
    }
    double s = ((double)f0 + (double)f1) + ((double)f2 + (double)f3);
#pragma unroll
    for (int o = 16; o > 0; o >>= 1) s += __shfl_xor_sync(0xFFFFFFFFu, s, o);

    __shared__ double sums[NSUM];
    __shared__ double ratios[13];
    if (wid < NSUM && lid == 0) sums[wid] = s;
    __syncthreads();

    if (threadIdx.x < 13)
        ratios[threadIdx.x] = sums[threadIdx.x] / (sums[13 + threadIdx.x] + 1e-5);
    __syncthreads();

    if (threadIdx.x == 0) {
        double accv = 0.0;
#pragma unroll
        for (int k = 0; k < 13; ++k) accv += ratios[k];
        const double bce = -sums[26] * inv_n * 0.6931471805599453; // log2 -> ln
        out[0] = (float)(bce + 1.0 - accv / 13.0);
    }
}

extern "C" void kernel_launch(void* const* d_in, const int* in_sizes, int n_in,
                              void* d_out, int out_size)
{
    const float* in = (const float*)d_in[0];
    const float* tg = (const float*)d_in[1];
    float* out = (float*)d_out;
    const int n = in_sizes[0];   // 18874368

    gc3d_main_kernel<<<NBLK, 128>>>(in, tg);
    gc3d_finalize_kernel<<<1, 864>>>(out, 1.0 / (double)n);
}

// round 10
// speedup vs baseline: 1.8307x; 1.0248x over previous
#include <cuda_runtime.h>

// GC_3D loss: BCE(mean) + 1 - (1/13) * sum_k [ sum(di_k*dt_k) / (sum(dt_k^2)+1e-5) ]
// Shape (4,1,128,192,192) f32, forward-z canonical offsets.
// R10: ZCHUNKS=8 (ZSTEP=16): halves per-chunk prologue/epilogue overhead,
//      single resident wave (2304 blocks), finalize input halved.

#define DX 192
#define DY 192
#define DZ 128
#define DXY (DX * DY)
#define NX4 48
#define NSUM 27
#define ZCHUNKS 8
#define ZSTEP (DZ / ZCHUNKS)   // 16
#define NBLK 2304               // 294912 threads / 128

__device__ float g_part[NSUM][NBLK];   // fully overwritten each run

__device__ __forceinline__ void ldwin(const float* __restrict__ p,
                                      int o_m1, int o_p4, float w[6]) {
    float4 v = *reinterpret_cast<const float4*>(p);
    w[0] = __ldg(p + o_m1);   // x-edge: o_m1=0 -> w[0]=center -> diff 0
    w[1] = v.x; w[2] = v.y; w[3] = v.z; w[4] = v.w;
    w[5] = __ldg(p + o_p4);   // x-edge: o_p4=3 -> w[5]=center -> diff 0
}

// One (row,dx) offset: 4 diffs per array. G: multiply dt by row flag (y-edge path only).
#define ACCUM(WI, WT, J, G, RF, D, Q) do {                                  \
    float di0 = (WI)[(J)]   - cI0; float dt0 = ((WT)[(J)]   - cT0);         \
    float di1 = (WI)[(J)+1] - cI1; float dt1 = ((WT)[(J)+1] - cT1);         \
    float di2 = (WI)[(J)+2] - cI2; float dt2 = ((WT)[(J)+2] - cT2);         \
    float di3 = (WI)[(J)+3] - cI3; float dt3 = ((WT)[(J)+3] - cT3);         \
    if (G) { dt0 *= (RF); dt1 *= (RF); dt2 *= (RF); dt3 *= (RF); }          \
    D = fmaf(di0, dt0, D); D = fmaf(di1, dt1, D);                           \
    D = fmaf(di2, dt2, D); D = fmaf(di3, dt3, D);                           \
    Q = fmaf(dt0, dt0, Q); Q = fmaf(dt1, dt1, Q);                           \
    Q = fmaf(dt2, dt2, Q); Q = fmaf(dt3, dt3, Q);                           \
} while (0)

#define ROW3(WI, WT, G, RF, K) do {                                         \
    ACCUM(WI, WT, 0, G, RF, dot[(K)],   den[(K)]);                          \
    ACCUM(WI, WT, 1, G, RF, dot[(K)+1], den[(K)+1]);                        \
    ACCUM(WI, WT, 2, G, RF, dot[(K)+2], den[(K)+2]);                        \
} while (0)

// BCE partial in log2 domain: lg2(1-i) + t*(lg2(i)-lg2(1-i))
#define BCE4(CI, CT) do {                                                   \
    float l1, l2;                                                           \
    l1 = __log2f(CI[1]); l2 = __log2f(1.0f - CI[1]); bce += l2 + CT[1]*(l1-l2); \
    l1 = __log2f(CI[2]); l2 = __log2f(1.0f - CI[2]); bce += l2 + CT[2]*(l1-l2); \
    l1 = __log2f(CI[3]); l2 = __log2f(1.0f - CI[3]); bce += l2 + CT[3]*(l1-l2); \
    l1 = __log2f(CI[4]); l2 = __log2f(1.0f - CI[4]); bce += l2 + CT[4]*(l1-l2); \
} while (0)

template<bool YG>
__device__ __forceinline__ void gc3d_march(
    const float* __restrict__ in, const float* __restrict__ tg,
    int base, int nsteps, bool do_epi,
    int o_m1, int o_p4, int dUp, int dDn,
    float fym, float fyp,
    float* dot, float* den, float& bce)
{
    float CWi[6], CWt[6], UWi[6], UWt[6];      // carried: center row, y+1 row
    ldwin(in + base,       o_m1, o_p4, CWi);
    ldwin(tg + base,       o_m1, o_p4, CWt);
    ldwin(in + base + dUp, o_m1, o_p4, UWi);
    ldwin(tg + base + dUp, o_m1, o_p4, UWt);

#pragma unroll 2
    for (int s = 0; s < nsteps; ++s) {
        const int baseN = base + DXY;
        float NmI[6], NmT[6], NcI[6], NcT[6], NpI[6], NpT[6];
        ldwin(in + baseN + dDn, o_m1, o_p4, NmI);
        ldwin(tg + baseN + dDn, o_m1, o_p4, NmT);
        ldwin(in + baseN,       o_m1, o_p4, NcI);
        ldwin(tg + baseN,       o_m1, o_p4, NcT);
        ldwin(in + baseN + dUp, o_m1, o_p4, NpI);
        ldwin(tg + baseN + dUp, o_m1, o_p4, NpT);

        const float cI0 = CWi[1], cI1 = CWi[2], cI2 = CWi[3], cI3 = CWi[4];
        const float cT0 = CWt[1], cT1 = CWt[2], cT2 = CWt[3], cT3 = CWt[4];

        BCE4(CWi, CWt);

        // k0: (0,0,+1) on center row — x-edges self-zero
        ACCUM(CWi, CWt, 2, false, 1.0f, dot[0], den[0]);
        // k1..3: (0,1,dx) on carried y+1 row
        ROW3(UWi, UWt, YG, fyp, 1);
        // k4..6: (1,-1,dx)
        ROW3(NmI, NmT, YG, fym, 4);
        // k7..9: (1,0,dx)
        ROW3(NcI, NcT, false, 1.0f, 7);
        // k10..12: (1,1,dx)
        ROW3(NpI, NpT, YG, fyp, 10);

#pragma unroll
        for (int j = 0; j < 6; ++j) {
            CWi[j] = NcI[j]; CWt[j] = NcT[j];
            UWi[j] = NpI[j]; UWt[j] = NpT[j];
        }
        base = baseN;
    }

    if (do_epi) {  // z = 127: only dz=0 offsets; no fresh loads
        const float cI0 = CWi[1], cI1 = CWi[2], cI2 = CWi[3], cI3 = CWi[4];
        const float cT0 = CWt[1], cT1 = CWt[2], cT2 = CWt[3], cT3 = CWt[4];
        BCE4(CWi, CWt);
        ACCUM(CWi, CWt, 2, false, 1.0f, dot[0], den[0]);
        ROW3(UWi, UWt, YG, fyp, 1);
    }
}

__global__ void __launch_bounds__(128) gc3d_main_kernel(
    const float* __restrict__ in, const float* __restrict__ tg)
{
    const int tid = blockIdx.x * blockDim.x + threadIdx.x;   // 0..294911
    const int x4 = tid % NX4;
    const int y  = (tid / NX4) % DY;
    const int t2 = tid / (NX4 * DY);   // 0..31
    const int zc = t2 & (ZCHUNKS - 1);
    const int b  = t2 / ZCHUNKS;
    const int z0 = zc * ZSTEP;

    int base = ((b * DZ + z0) * DY + y) * DX + x4 * 4;

    const int   o_m1 = (x4 == 0)       ? 0 : -1;
    const int   o_p4 = (x4 == NX4 - 1) ? 3 : 4;
    const int   dUp  = (y == DY - 1) ? 0 : DX;
    const int   dDn  = (y == 0)      ? 0 : -DX;
    const float fyp  = (y == DY - 1) ? 0.0f : 1.0f;
    const float fym  = (y == 0)      ? 0.0f : 1.0f;

    const int  nsteps = (zc == ZCHUNKS - 1) ? (ZSTEP - 1) : ZSTEP;
    const bool do_epi = (zc == ZCHUNKS - 1);

    float dot[13], den[13], bce = 0.0f;
#pragma unroll
    for (int k = 0; k < 13; ++k) { dot[k] = 0.0f; den[k] = 0.0f; }

    if (y == 0 || y == DY - 1)
        gc3d_march<true >(in, tg, base, nsteps, do_epi, o_m1, o_p4, dUp, dDn,
                          fym, fyp, dot, den, bce);
    else
        gc3d_march<false>(in, tg, base, nsteps, do_epi, o_m1, o_p4, dUp, dDn,
                          fym, fyp, dot, den, bce);

    // pack 27 partials, warp butterfly, block reduce, overwrite block slot
    float acc[NSUM];
#pragma unroll
    for (int k = 0; k < 13; ++k) { acc[k] = dot[k]; acc[13 + k] = den[k]; }
    acc[26] = bce;

#pragma unroll
    for (int i = 0; i < NSUM; ++i) {
        float v = acc[i];
#pragma unroll
        for (int o = 16; o > 0; o >>= 1) v += __shfl_xor_sync(0xFFFFFFFFu, v, o);
        acc[i] = v;
    }

    __shared__ float sh[4][NSUM];
    const int wid = threadIdx.x >> 5;
    const int lid = threadIdx.x & 31;
    if (lid == 0) {
#pragma unroll
        for (int i = 0; i < NSUM; ++i) sh[wid][i] = acc[i];
    }
    __syncthreads();
    if (wid == 0 && lid < NSUM) {
        g_part[lid][blockIdx.x] = sh[0][lid] + sh[1][lid] + sh[2][lid] + sh[3][lid];
    }
}

// 27 warps: warp i reduces g_part[i][*]. float4 loads + f32 accumulation;
// FP64 only in the 5-step butterfly and the 13 divides.
__global__ void __launch_bounds__(864) gc3d_finalize_kernel(float* out, double inv_n) {
    const int wid = threadIdx.x >> 5;
    const int lid = threadIdx.x & 31;

    float f0 = 0.0f, f1 = 0.0f, f2 = 0.0f, f3 = 0.0f;
    if (wid < NSUM) {
        const float4* row = reinterpret_cast<const float4*>(g_part[wid]);
#pragma unroll
        for (int j = 0; j < NBLK / 4 / 32; ++j) {       // 18 iterations
            float4 v = __ldg(row + lid + 32 * j);
            f0 += v.x; f1 += v.y; f2 += v.z; f3 += v.w;
        }
    }
    double s = ((double)f0 + (double)f1) + ((double)f2 + (double)f3);
#pragma unroll
    for (int o = 16; o > 0; o >>= 1) s += __shfl_xor_sync(0xFFFFFFFFu, s, o);

    __shared__ double sums[NSUM];
    __shared__ double ratios[13];
    if (wid < NSUM && lid == 0) sums[wid] = s;
    __syncthreads();

    if (threadIdx.x < 13)
        ratios[threadIdx.x] = sums[threadIdx.x] / (sums[13 + threadIdx.x] + 1e-5);
    __syncthreads();

    if (threadIdx.x == 0) {
        double accv = 0.0;
#pragma unroll
        for (int k = 0; k < 13; ++k) accv += ratios[k];
        const double bce = -sums[26] * inv_n * 0.6931471805599453; // log2 -> ln
        out[0] = (float)(bce + 1.0 - accv / 13.0);
    }
}

extern "C" void kernel_launch(void* const* d_in, const int* in_sizes, int n_in,
                              void* d_out, int out_size)
{
    const float* in = (const float*)d_in[0];
    const float* tg = (const float*)d_in[1];
    float* out = (float*)d_out;
    const int n = in_sizes[0];   // 18874368

    gc3d_main_kernel<<<NBLK, 128>>>(in, tg);
    gc3d_finalize_kernel<<<1, 864>>>(out, 1.0 / (double)n);
}

// round 11
// speedup vs baseline: 1.9724x; 1.0774x over previous
#include <cuda_runtime.h>

// GC_3D loss: BCE(mean) + 1 - (1/13) * sum_k [ sum(di_k*dt_k) / (sum(dt_k^2)+1e-5) ]
// Shape (4,1,128,192,192) f32, forward-z canonical offsets.
// R11: R10 main kernel + float atomicAdd cross-block reduction (hidden under
//      main's execution) + tiny 32-thread finalize that self-re-zeros g_sums.

#define DX 192
#define DY 192
#define DZ 128
#define DXY (DX * DY)
#define NX4 48
#define NSUM 27
#define ZCHUNKS 8
#define ZSTEP (DZ / ZCHUNKS)   // 16
#define NBLK 2304               // 294912 threads / 128

__device__ float g_sums[NSUM];   // zero at load; finalize re-zeros after reading

__device__ __forceinline__ void ldwin(const float* __restrict__ p,
                                      int o_m1, int o_p4, float w[6]) {
    float4 v = *reinterpret_cast<const float4*>(p);
    w[0] = __ldg(p + o_m1);   // x-edge: o_m1=0 -> w[0]=center -> diff 0
    w[1] = v.x; w[2] = v.y; w[3] = v.z; w[4] = v.w;
    w[5] = __ldg(p + o_p4);   // x-edge: o_p4=3 -> w[5]=center -> diff 0
}

// One (row,dx) offset: 4 diffs per array. G: multiply dt by row flag (y-edge path only).
#define ACCUM(WI, WT, J, G, RF, D, Q) do {                                  \
    float di0 = (WI)[(J)]   - cI0; float dt0 = ((WT)[(J)]   - cT0);         \
    float di1 = (WI)[(J)+1] - cI1; float dt1 = ((WT)[(J)+1] - cT1);         \
    float di2 = (WI)[(J)+2] - cI2; float dt2 = ((WT)[(J)+2] - cT2);         \
    float di3 = (WI)[(J)+3] - cI3; float dt3 = ((WT)[(J)+3] - cT3);         \
    if (G) { dt0 *= (RF); dt1 *= (RF); dt2 *= (RF); dt3 *= (RF); }          \
    D = fmaf(di0, dt0, D); D = fmaf(di1, dt1, D);                           \
    D = fmaf(di2, dt2, D); D = fmaf(di3, dt3, D);                           \
    Q = fmaf(dt0, dt0, Q); Q = fmaf(dt1, dt1, Q);                           \
    Q = fmaf(dt2, dt2, Q); Q = fmaf(dt3, dt3, Q);                           \
} while (0)

#define ROW3(WI, WT, G, RF, K) do {                                         \
    ACCUM(WI, WT, 0, G, RF, dot[(K)],   den[(K)]);                          \
    ACCUM(WI, WT, 1, G, RF, dot[(K)+1], den[(K)+1]);                        \
    ACCUM(WI, WT, 2, G, RF, dot[(K)+2], den[(K)+2]);                        \
} while (0)

// BCE partial in log2 domain: lg2(1-i) + t*(lg2(i)-lg2(1-i))
#define BCE4(CI, CT) do {                                                   \
    float l1, l2;                                                           \
    l1 = __log2f(CI[1]); l2 = __log2f(1.0f - CI[1]); bce += l2 + CT[1]*(l1-l2); \
    l1 = __log2f(CI[2]); l2 = __log2f(1.0f - CI[2]); bce += l2 + CT[2]*(l1-l2); \
    l1 = __log2f(CI[3]); l2 = __log2f(1.0f - CI[3]); bce += l2 + CT[3]*(l1-l2); \
    l1 = __log2f(CI[4]); l2 = __log2f(1.0f - CI[4]); bce += l2 + CT[4]*(l1-l2); \
} while (0)

template<bool YG>
__device__ __forceinline__ void gc3d_march(
    const float* __restrict__ in, const float* __restrict__ tg,
    int base, int nsteps, bool do_epi,
    int o_m1, int o_p4, int dUp, int dDn,
    float fym, float fyp,
    float* dot, float* den, float& bce)
{
    float CWi[6], CWt[6], UWi[6], UWt[6];      // carried: center row, y+1 row
    ldwin(in + base,       o_m1, o_p4, CWi);
    ldwin(tg + base,       o_m1, o_p4, CWt);
    ldwin(in + base + dUp, o_m1, o_p4, UWi);
    ldwin(tg + base + dUp, o_m1, o_p4, UWt);

#pragma unroll 2
    for (int s = 0; s < nsteps; ++s) {
        const int baseN = base + DXY;
        float NmI[6], NmT[6], NcI[6], NcT[6], NpI[6], NpT[6];
        ldwin(in + baseN + dDn, o_m1, o_p4, NmI);
        ldwin(tg + baseN + dDn, o_m1, o_p4, NmT);
        ldwin(in + baseN,       o_m1, o_p4, NcI);
        ldwin(tg + baseN,       o_m1, o_p4, NcT);
        ldwin(in + baseN + dUp, o_m1, o_p4, NpI);
        ldwin(tg + baseN + dUp, o_m1, o_p4, NpT);

        const float cI0 = CWi[1], cI1 = CWi[2], cI2 = CWi[3], cI3 = CWi[4];
        const float cT0 = CWt[1], cT1 = CWt[2], cT2 = CWt[3], cT3 = CWt[4];

        BCE4(CWi, CWt);

        // k0: (0,0,+1) on center row — x-edges self-zero
        ACCUM(CWi, CWt, 2, false, 1.0f, dot[0], den[0]);
        // k1..3: (0,1,dx) on carried y+1 row
        ROW3(UWi, UWt, YG, fyp, 1);
        // k4..6: (1,-1,dx)
        ROW3(NmI, NmT, YG, fym, 4);
        // k7..9: (1,0,dx)
        ROW3(NcI, NcT, false, 1.0f, 7);
        // k10..12: (1,1,dx)
        ROW3(NpI, NpT, YG, fyp, 10);

#pragma unroll
        for (int j = 0; j < 6; ++j) {
            CWi[j] = NcI[j]; CWt[j] = NcT[j];
            UWi[j] = NpI[j]; UWt[j] = NpT[j];
        }
        base = baseN;
    }

    if (do_epi) {  // z = 127: only dz=0 offsets; no fresh loads
        const float cI0 = CWi[1], cI1 = CWi[2], cI2 = CWi[3], cI3 = CWi[4];
        const float cT0 = CWt[1], cT1 = CWt[2], cT2 = CWt[3], cT3 = CWt[4];
        BCE4(CWi, CWt);
        ACCUM(CWi, CWt, 2, false, 1.0f, dot[0], den[0]);
        ROW3(UWi, UWt, YG, fyp, 1);
    }
}

__global__ void __launch_bounds__(128) gc3d_main_kernel(
    const float* __restrict__ in, const float* __restrict__ tg)
{
    const int tid = blockIdx.x * blockDim.x + threadIdx.x;   // 0..294911
    const int x4 = tid % NX4;
    const int y  = (tid / NX4) % DY;
    const int t2 = tid / (NX4 * DY);   // 0..31
    const int zc = t2 & (ZCHUNKS - 1);
    const int b  = t2 / ZCHUNKS;
    const int z0 = zc * ZSTEP;

    int base = ((b * DZ + z0) * DY + y) * DX + x4 * 4;

    const int   o_m1 = (x4 == 0)       ? 0 : -1;
    const int   o_p4 = (x4 == NX4 - 1) ? 3 : 4;
    const int   dUp  = (y == DY - 1) ? 0 : DX;
    const int   dDn  = (y == 0)      ? 0 : -DX;
    const float fyp  = (y == DY - 1) ? 0.0f : 1.0f;
    const float fym  = (y == 0)      ? 0.0f : 1.0f;

    const int  nsteps = (zc == ZCHUNKS - 1) ? (ZSTEP - 1) : ZSTEP;
    const bool do_epi = (zc == ZCHUNKS - 1);

    float dot[13], den[13], bce = 0.0f;
#pragma unroll
    for (int k = 0; k < 13; ++k) { dot[k] = 0.0f; den[k] = 0.0f; }

    if (y == 0 || y == DY - 1)
        gc3d_march<true >(in, tg, base, nsteps, do_epi, o_m1, o_p4, dUp, dDn,
                          fym, fyp, dot, den, bce);
    else
        gc3d_march<false>(in, tg, base, nsteps, do_epi, o_m1, o_p4, dUp, dDn,
                          fym, fyp, dot, den, bce);

    // pack 27 partials, warp butterfly, block reduce, float atomic into g_sums
    float acc[NSUM];
#pragma unroll
    for (int k = 0; k < 13; ++k) { acc[k] = dot[k]; acc[13 + k] = den[k]; }
    acc[26] = bce;

#pragma unroll
    for (int i = 0; i < NSUM; ++i) {
        float v = acc[i];
#pragma unroll
        for (int o = 16; o > 0; o >>= 1) v += __shfl_xor_sync(0xFFFFFFFFu, v, o);
        acc[i] = v;
    }

    __shared__ float sh[4][NSUM];
    const int wid = threadIdx.x >> 5;
    const int lid = threadIdx.x & 31;
    if (lid == 0) {
#pragma unroll
        for (int i = 0; i < NSUM; ++i) sh[wid][i] = acc[i];
    }
    __syncthreads();
    if (wid == 0 && lid < NSUM) {
        atomicAdd(&g_sums[lid], sh[0][lid] + sh[1][lid] + sh[2][lid] + sh[3][lid]);
    }
}

// Tiny finalize: read 27 sums, 13 parallel DP divides, write scalar,
// then re-zero g_sums so the next graph replay starts clean.
__global__ void gc3d_finalize_kernel(float* out, double inv_n) {
    const int t = threadIdx.x;

    __shared__ double sums[NSUM];
    __shared__ double ratios[13];
    if (t < NSUM) sums[t] = (double)g_sums[t];
    __syncthreads();

    if (t < 13)
        ratios[t] = sums[t] / (sums[13 + t] + 1e-5);
    __syncthreads();

    if (t == 0) {
        double accv = 0.0;
#pragma unroll
        for (int k = 0; k < 13; ++k) accv += ratios[k];
        const double bce = -sums[26] * inv_n * 0.6931471805599453; // log2 -> ln
        out[0] = (float)(bce + 1.0 - accv / 13.0);
    }

    if (t < NSUM) g_sums[t] = 0.0f;   // reset for next replay
}

extern "C" void kernel_launch(void* const* d_in, const int* in_sizes, int n_in,
                              void* d_out, int out_size)
{
    const float* in = (const float*)d_in[0];
    const float* tg = (const float*)d_in[1];
    float* out = (float*)d_out;
    const int n = in_sizes[0];   // 18874368

    gc3d_main_kernel<<<NBLK, 128>>>(in, tg);
    gc3d_finalize_kernel<<<1, 32>>>(out, 1.0 / (double)n);
}